// round 8
// baseline (speedup 1.0000x reference)
#include <cuda_runtime.h>
#include <cuda_bf16.h>
#include <cstdint>

#define BATCH  512
#define NP1    257
#define DP1    129
#define NLAYER 4
#define ZGST   152     // global Zh row stride (halves), 304B rows, uint4-aligned
#define GST    152     // G/S/W smem row stride (conflict-free, >=144 cols)
#define S3ST   40      // P3 stage row stride (halves): r*20 mod 32 distinct -> CF
#define NTHR   288

typedef __nv_bfloat16 bf16;

__device__ bf16 g_PQ [NLAYER * 2 * 128 * 128];         // bf16 P,Q weights
__device__ bf16 g_Zhg[(size_t)BATCH * NP1 * ZGST];     // bf16 Z shadow (global, L2-hot)
__device__ bf16 g_Ac [(size_t)BATCH * NP1 * DP1];      // running sum R_k * gamma_k

// ------------------------------ mma helpers --------------------------------
__device__ __forceinline__ uint32_t smaddr(const void* p) {
    return (uint32_t)__cvta_generic_to_shared(p);
}
__device__ __forceinline__ void ldmx4(uint32_t* r, uint32_t a) {
    asm volatile("ldmatrix.sync.aligned.m8n8.x4.shared.b16 {%0,%1,%2,%3}, [%4];"
                 : "=r"(r[0]), "=r"(r[1]), "=r"(r[2]), "=r"(r[3]) : "r"(a));
}
__device__ __forceinline__ void ldmx4t(uint32_t* r, uint32_t a) {
    asm volatile("ldmatrix.sync.aligned.m8n8.x4.trans.shared.b16 {%0,%1,%2,%3}, [%4];"
                 : "=r"(r[0]), "=r"(r[1]), "=r"(r[2]), "=r"(r[3]) : "r"(a));
}
__device__ __forceinline__ void mma16816(float* c, const uint32_t* a, const uint32_t* b) {
    asm volatile("mma.sync.aligned.m16n8k16.row.col.f32.bf16.bf16.f32 "
                 "{%0,%1,%2,%3}, {%4,%5,%6,%7}, {%8,%9}, {%0,%1,%2,%3};"
                 : "+f"(c[0]), "+f"(c[1]), "+f"(c[2]), "+f"(c[3])
                 : "r"(a[0]), "r"(a[1]), "r"(a[2]), "r"(a[3]), "r"(b[0]), "r"(b[1]));
}
__device__ __forceinline__ __nv_bfloat162 pack2(float a, float b) {
    __nv_bfloat162 v;
    v.x = __float2bfloat16(a);
    v.y = __float2bfloat16(b);
    return v;
}

// ------------------------------- init kernels -------------------------------
__global__ void k_init(const float* __restrict__ Z) {
    size_t i = (size_t)blockIdx.x * blockDim.x + threadIdx.x;
    size_t total = (size_t)BATCH * NP1 * ZGST;
    if (i >= total) return;
    size_t row = i / ZGST;
    int c = (int)(i % ZGST);
    float v = (c < DP1) ? Z[row * DP1 + c] : 0.0f;
    g_Zhg[i] = __float2bfloat16(v);
}

__global__ void k_convPQ(const float* __restrict__ allparam) {
    int i = blockIdx.x * blockDim.x + threadIdx.x;
    if (i < NLAYER * 2 * 128 * 128) g_PQ[i] = __float2bfloat16(allparam[i]);
}

// ------------------------------- k_fused ------------------------------------
// One CTA per batch, 4 layers. G/S/W resident in smem; Zh + Ac stream via
// global (L2-hot) through small staged tiles -> 110.6KB smem -> 2 CTAs/SM.
extern __shared__ bf16 sm_f[];

__global__ __launch_bounds__(NTHR, 2) void k_fused(const float* __restrict__ Zin0,
                                                   const float* __restrict__ gamma,
                                                   float* __restrict__ Zio) {
    bf16* Gs = sm_f;                 // 144 x 152 (G, later W)
    bf16* Ss = Gs + 144 * GST;       // 144 x 152 (S)
    bf16* St = Ss + 144 * GST;       // stages: 2 x 5760 halves (union P1/P3)

    int b = blockIdx.x;
    const float* Zb0 = Zin0 + (size_t)b * NP1 * DP1;
    float*       Zo  = Zio  + (size_t)b * NP1 * DP1;
    bf16*        Zg  = g_Zhg + (size_t)b * NP1 * ZGST;
    bf16*        Acb = g_Ac  + (size_t)b * NP1 * DP1;

    int tid = threadIdx.x, lane = tid & 31, warp = tid >> 5;
    int wm = (warp / 3) * 48, wn = (warp % 3) * 48;
    int mat = lane >> 3, l7 = lane & 7;
    int g = lane >> 2, t4 = lane & 3;

    float acc[3][3][2][4];
    uint32_t afr[3][4], bfr[3][4];

    auto zero_acc = [&]() {
#pragma unroll
        for (int a = 0; a < 3; a++)
#pragma unroll
            for (int c = 0; c < 3; c++)
#pragma unroll
                for (int h = 0; h < 2; h++)
#pragma unroll
                    for (int e = 0; e < 4; e++) acc[a][c][h][e] = 0.0f;
    };
    auto do_mmas = [&]() {
#pragma unroll
        for (int ni = 0; ni < 3; ni++)
#pragma unroll
            for (int mi = 0; mi < 3; mi++) {
                mma16816(acc[mi][ni][0], afr[mi], bfr[ni] + 0);
                mma16816(acc[mi][ni][1], afr[mi], bfr[ni] + 2);
            }
    };

    // P1 stage copy indices: 288 = 16 rows x 18 uint4
    int p1r = tid / 18, p1c = (tid % 18) * 8;
    // P3 stage copy indices: 288 = 144 rows x 2 uint4
    int p3r = tid >> 1, p3c = (tid & 1) * 8;

    for (int l = 0; l < NLAYER; l++) {
        const bf16* P = g_PQ + ((size_t)l * 2 + 0) * 128 * 128;
        const bf16* Q = g_PQ + ((size_t)l * 2 + 1) * 128 * 128;
        const float* gml = gamma + (size_t)l * NP1 * DP1;
        const float* Zi  = (l == 0) ? Zb0 : Zo;

        // ========== Phase 1: G = Zh[:256]^T Zh[:256]  (K=256, 16 stages) =====
        zero_acc();
        {
            uint4 v = *(const uint4*)&Zg[(size_t)p1r * ZGST + p1c];
            *(uint4*)&St[p1r * 152 + p1c] = v;
        }
        __syncthreads();
        for (int s = 0; s < 16; s++) {
            uint4 nxt;
            if (s < 15)
                nxt = *(const uint4*)&Zg[(size_t)(16 * (s + 1) + p1r) * ZGST + p1c];
            const bf16* sb = St + (s & 1) * (16 * 152);
            int arow = ((mat >> 1) << 3) + l7;
#pragma unroll
            for (int mi = 0; mi < 3; mi++)
                ldmx4t(afr[mi], smaddr(&sb[arow * 152 + wm + mi * 16 + ((mat & 1) << 3)]));
            int brow = ((mat & 1) << 3) + l7;
#pragma unroll
            for (int ni = 0; ni < 3; ni++)
                ldmx4t(bfr[ni], smaddr(&sb[brow * 152 + wn + ni * 16 + ((mat >> 1) << 3)]));
            do_mmas();
            if (s < 15)
                *(uint4*)&St[((s + 1) & 1) * (16 * 152) + p1r * 152 + p1c] = nxt;
            __syncthreads();
        }
#pragma unroll
        for (int mi = 0; mi < 3; mi++)
#pragma unroll
            for (int ni = 0; ni < 3; ni++)
#pragma unroll
                for (int h = 0; h < 2; h++) {
                    float* c = acc[mi][ni][h];
                    int row = wm + mi * 16 + g;
                    int col = wn + ni * 16 + h * 8 + 2 * t4;
                    *(__nv_bfloat162*)&Gs[row * GST + col]       = pack2(c[0], c[1]);
                    *(__nv_bfloat162*)&Gs[(row + 8) * GST + col] = pack2(c[2], c[3]);
                }
        __syncthreads();

        // ========== Phase 2a: S = G @ P^T  (K=128) ==========================
        zero_acc();
        for (int kk = 0; kk < 128; kk += 16) {
#pragma unroll
            for (int mi = 0; mi < 3; mi++) {
                int arow = wm + mi * 16 + ((mat & 1) << 3) + l7;
                ldmx4(afr[mi], smaddr(&Gs[arow * GST + kk + ((mat >> 1) << 3)]));
            }
#pragma unroll
            for (int ni = 0; ni < 3; ni++)
#pragma unroll
                for (int h = 0; h < 2; h++) {
                    int j = wn + ni * 16 + h * 8 + g;
                    if (j < 128) {
                        bfr[ni][2 * h + 0] = *(const uint32_t*)&P[j * 128 + kk + 2 * t4];
                        bfr[ni][2 * h + 1] = *(const uint32_t*)&P[j * 128 + kk + 8 + 2 * t4];
                    } else {
                        bfr[ni][2 * h + 0] = 0u;
                        bfr[ni][2 * h + 1] = 0u;
                    }
                }
            do_mmas();
        }
        // store S; fold in S[:,128] = G[:,128]
#pragma unroll
        for (int mi = 0; mi < 3; mi++)
#pragma unroll
            for (int ni = 0; ni < 3; ni++)
#pragma unroll
                for (int h = 0; h < 2; h++) {
                    float* c = acc[mi][ni][h];
                    int row = wm + mi * 16 + g;
                    int col = wn + ni * 16 + h * 8 + 2 * t4;
                    __nv_bfloat162 v0 = pack2(c[0], c[1]);
                    __nv_bfloat162 v1 = pack2(c[2], c[3]);
                    if (col == 128) {
                        v0.x = Gs[row * GST + 128];
                        v1.x = Gs[(row + 8) * GST + 128];
                    }
                    *(__nv_bfloat162*)&Ss[row * GST + col]       = v0;
                    *(__nv_bfloat162*)&Ss[(row + 8) * GST + col] = v1;
                }
        __syncthreads();

        // ========== Phase 2b: W = Q @ S  (K=128, into Gs) ====================
        zero_acc();
        for (int kk = 0; kk < 128; kk += 16) {
#pragma unroll
            for (int mi = 0; mi < 3; mi++) {
                int m = wm + mi * 16 + g;
                afr[mi][0] = (m     < 128) ? *(const uint32_t*)&Q[m * 128 + kk + 2 * t4]           : 0u;
                afr[mi][1] = (m + 8 < 128) ? *(const uint32_t*)&Q[(m + 8) * 128 + kk + 2 * t4]     : 0u;
                afr[mi][2] = (m     < 128) ? *(const uint32_t*)&Q[m * 128 + kk + 8 + 2 * t4]       : 0u;
                afr[mi][3] = (m + 8 < 128) ? *(const uint32_t*)&Q[(m + 8) * 128 + kk + 8 + 2 * t4] : 0u;
            }
            int brow = kk + ((mat & 1) << 3) + l7;
#pragma unroll
            for (int ni = 0; ni < 3; ni++)
                ldmx4t(bfr[ni], smaddr(&Ss[brow * GST + wn + ni * 16 + ((mat >> 1) << 3)]));
            do_mmas();
        }
#pragma unroll
        for (int mi = 0; mi < 3; mi++)
#pragma unroll
            for (int ni = 0; ni < 3; ni++)
#pragma unroll
                for (int h = 0; h < 2; h++) {
                    float* c = acc[mi][ni][h];
                    int row = wm + mi * 16 + g;
                    int col = wn + ni * 16 + h * 8 + 2 * t4;
                    *(__nv_bfloat162*)&Gs[row * GST + col]       = pack2(c[0], c[1]);
                    *(__nv_bfloat162*)&Gs[(row + 8) * GST + col] = pack2(c[2], c[3]);
                }
        __syncthreads();

        // ========== Phase 3: R = Zh @ W / 256  (K=128: W rows>=128 are 0) ====
        // chunk 0: token rows 0..143 ; chunk 1: rows 113..256 (n<144 discarded)
#pragma unroll
        for (int c0 = 0; c0 < 2; c0++) {
            int base = c0 ? 113 : 0;
            zero_acc();
            {
                uint4 v = *(const uint4*)&Zg[(size_t)(base + p3r) * ZGST + p3c];
                *(uint4*)&St[p3r * S3ST + p3c] = v;
            }
            __syncthreads();
            for (int s = 0; s < 8; s++) {
                uint4 nxt;
                if (s < 7)
                    nxt = *(const uint4*)&Zg[(size_t)(base + p3r) * ZGST + 16 * (s + 1) + p3c];
                const bf16* sb = St + (s & 1) * 5760;
#pragma unroll
                for (int mi = 0; mi < 3; mi++) {
                    int arow = wm + mi * 16 + ((mat & 1) << 3) + l7;
                    ldmx4(afr[mi], smaddr(&sb[arow * S3ST + ((mat >> 1) << 3)]));
                }
                int brow = 16 * s + ((mat & 1) << 3) + l7;
#pragma unroll
                for (int ni = 0; ni < 3; ni++)
                    ldmx4t(bfr[ni], smaddr(&Gs[brow * GST + wn + ni * 16 + ((mat >> 1) << 3)]));
                do_mmas();
                if (s < 7)
                    *(uint4*)&St[((s + 1) & 1) * 5760 + p3r * S3ST + p3c] = nxt;
                __syncthreads();
            }

            const float inv = 1.0f / 256.0f;
#pragma unroll
            for (int mi = 0; mi < 3; mi++)
#pragma unroll
                for (int ni = 0; ni < 3; ni++)
#pragma unroll
                    for (int h = 0; h < 2; h++) {
                        float* cc = acc[mi][ni][h];
                        int row0 = wm + mi * 16 + g;
                        int col0 = wn + ni * 16 + h * 8 + 2 * t4;
#pragma unroll
                        for (int e = 0; e < 4; e++) {
                            int n = base + row0 + ((e >> 1) ? 8 : 0);
                            int j = col0 + (e & 1);
                            if (n < NP1 && j < DP1 && (c0 == 0 || n >= 144)) {
                                size_t fi = (size_t)n * DP1 + j;
                                float r = cc[e] * inv;
                                float a = (l == 0) ? 0.0f
                                                   : __bfloat162float(Acb[fi]);
                                float zo = Zi[fi] + r + a;
                                Zo[fi]  = zo;
                                Acb[fi] = __float2bfloat16(a + r * gml[fi]);
                                Zg[(size_t)n * ZGST + j] = __float2bfloat16(zo);
                            }
                        }
                    }
            __syncthreads();
        }
    }
}

// ------------------------------ kernel_launch -------------------------------
extern "C" void kernel_launch(void* const* d_in, const int* in_sizes, int n_in,
                              void* d_out, int out_size) {
    const float* Z        = (const float*)d_in[0];
    const float* allparam = (const float*)d_in[1];
    const float* gamma    = (const float*)d_in[2];

    const int smem_bytes = (2 * 144 * GST + 2 * 5760) * (int)sizeof(bf16); // 110592
    cudaFuncSetAttribute(k_fused, cudaFuncAttributeMaxDynamicSharedMemorySize,
                         smem_bytes);

    size_t ztot = (size_t)BATCH * NP1 * ZGST;
    k_init<<<(int)((ztot + 255) / 256), 256>>>(Z);
    k_convPQ<<<(NLAYER * 2 * 128 * 128 + 255) / 256, 256>>>(allparam);
    k_fused<<<BATCH, NTHR, smem_bytes>>>(Z, gamma, (float*)d_out);
}

// round 9
// speedup vs baseline: 2.0700x; 2.0700x over previous
#include <cuda_runtime.h>
#include <cuda_bf16.h>
#include <cstdint>

#define BATCH  512
#define NP1    257
#define DP1    129
#define NLAYER 4
#define ZST    152     // Zh smem row stride (halves)
#define GST    152     // G/S/W smem row stride
#define AST    129     // acc smem row stride (scalar access only)

typedef __nv_bfloat16 bf16;

__device__ bf16 g_PQ[NLAYER * 2 * 128 * 128];   // bf16 P,Q weights

// ------------------------------ mma helpers --------------------------------
__device__ __forceinline__ uint32_t smaddr(const void* p) {
    return (uint32_t)__cvta_generic_to_shared(p);
}
__device__ __forceinline__ void ldmx4(uint32_t* r, uint32_t a) {
    asm volatile("ldmatrix.sync.aligned.m8n8.x4.shared.b16 {%0,%1,%2,%3}, [%4];"
                 : "=r"(r[0]), "=r"(r[1]), "=r"(r[2]), "=r"(r[3]) : "r"(a));
}
__device__ __forceinline__ void ldmx4t(uint32_t* r, uint32_t a) {
    asm volatile("ldmatrix.sync.aligned.m8n8.x4.trans.shared.b16 {%0,%1,%2,%3}, [%4];"
                 : "=r"(r[0]), "=r"(r[1]), "=r"(r[2]), "=r"(r[3]) : "r"(a));
}
__device__ __forceinline__ void mma16816(float* c, const uint32_t* a, const uint32_t* b) {
    asm volatile("mma.sync.aligned.m16n8k16.row.col.f32.bf16.bf16.f32 "
                 "{%0,%1,%2,%3}, {%4,%5,%6,%7}, {%8,%9}, {%0,%1,%2,%3};"
                 : "+f"(c[0]), "+f"(c[1]), "+f"(c[2]), "+f"(c[3])
                 : "r"(a[0]), "r"(a[1]), "r"(a[2]), "r"(a[3]), "r"(b[0]), "r"(b[1]));
}
__device__ __forceinline__ __nv_bfloat162 pack2(float a, float b) {
    __nv_bfloat162 v;
    v.x = __float2bfloat16(a);
    v.y = __float2bfloat16(b);
    return v;
}

// ------------------------------- convPQ -------------------------------------
__global__ void k_convPQ(const float* __restrict__ allparam) {
    int i = blockIdx.x * blockDim.x + threadIdx.x;
    if (i < NLAYER * 2 * 128 * 128) g_PQ[i] = __float2bfloat16(allparam[i]);
}

// ------------------------------- k_fused ------------------------------------
extern __shared__ bf16 sm_f[];

__global__ __launch_bounds__(288, 1) void k_fused(const float* __restrict__ Zin0,
                                                  const float* __restrict__ gamma,
                                                  float* __restrict__ Zio) {
    bf16* Zh = sm_f;                       // 257 x 152
    bf16* Gs = Zh + 257 * ZST;             // 144 x 152  (Gram, later W)
    bf16* Ss = Gs + 144 * GST;             // 144 x 152  (S = G P^T)
    bf16* Ac = Ss + 144 * GST;             // 257 x 129  (bf16 running acc)

    int b = blockIdx.x;
    const float* Zb0 = Zin0 + (size_t)b * NP1 * DP1;
    float*       Zo  = Zio  + (size_t)b * NP1 * DP1;

    int tid = threadIdx.x, lane = tid & 31, warp = tid >> 5;
    int wm = (warp / 3) * 48, wn = (warp % 3) * 48;
    int mat = lane >> 3, l7 = lane & 7;
    int g = lane >> 2, t4 = lane & 3;

    // ---------------- init: Zh from input Z; acc = 0 ----------------
    for (int i = tid; i < 257 * 38; i += 288) {
        int r = i / 38, c4 = (i % 38) * 4;
#pragma unroll
        for (int u = 0; u < 4; u++) {
            int j = c4 + u;
            float v = (j < DP1) ? Zb0[(size_t)r * DP1 + j] : 0.0f;
            Zh[r * ZST + j] = __float2bfloat16(v);
        }
    }
    for (int i = tid; i < 257 * AST; i += 288)
        Ac[i] = __float2bfloat16(0.0f);
    __syncthreads();

    float acc[3][3][2][4];
    uint32_t afr[2][3][4], bfr[2][3][4];

    for (int l = 0; l < NLAYER; l++) {
        const bf16* P = g_PQ + ((size_t)l * 2 + 0) * 128 * 128;
        const bf16* Q = g_PQ + ((size_t)l * 2 + 1) * 128 * 128;
        const float* gml = gamma + (size_t)l * NP1 * DP1;
        const float* Zi  = (l == 0) ? Zb0 : Zo;

        // -- fragment loaders (double-buffered call sites) --
        auto p1_loadA = [&](int kk, uint32_t fr[3][4]) {
            int arow = kk + ((mat >> 1) << 3) + l7;
#pragma unroll
            for (int mi = 0; mi < 3; mi++)
                ldmx4t(fr[mi], smaddr(&Zh[arow * ZST + wm + mi * 16 + ((mat & 1) << 3)]));
        };
        auto p1_loadB = [&](int kk, uint32_t fr[3][4]) {
            int brow = kk + ((mat & 1) << 3) + l7;
#pragma unroll
            for (int ni = 0; ni < 3; ni++)
                ldmx4t(fr[ni], smaddr(&Zh[brow * ZST + wn + ni * 16 + ((mat >> 1) << 3)]));
        };
        auto p2a_loadA = [&](int kk, uint32_t fr[3][4]) {
#pragma unroll
            for (int mi = 0; mi < 3; mi++) {
                int arow = wm + mi * 16 + ((mat & 1) << 3) + l7;
                ldmx4(fr[mi], smaddr(&Gs[arow * GST + kk + ((mat >> 1) << 3)]));
            }
        };
        auto p2a_loadB = [&](int kk, uint32_t fr[3][4]) {
#pragma unroll
            for (int ni = 0; ni < 3; ni++)
#pragma unroll
                for (int h = 0; h < 2; h++) {
                    int j = wn + ni * 16 + h * 8 + g;
                    if (j < 128) {
                        fr[ni][2 * h + 0] = *(const uint32_t*)&P[j * 128 + kk + 2 * t4];
                        fr[ni][2 * h + 1] = *(const uint32_t*)&P[j * 128 + kk + 8 + 2 * t4];
                    } else {
                        fr[ni][2 * h + 0] = 0u;
                        fr[ni][2 * h + 1] = 0u;
                    }
                }
        };
        auto p2b_loadA = [&](int kk, uint32_t fr[3][4]) {
#pragma unroll
            for (int mi = 0; mi < 3; mi++) {
                int m = wm + mi * 16 + g;
                fr[mi][0] = (m     < 128) ? *(const uint32_t*)&Q[m * 128 + kk + 2 * t4]           : 0u;
                fr[mi][1] = (m + 8 < 128) ? *(const uint32_t*)&Q[(m + 8) * 128 + kk + 2 * t4]     : 0u;
                fr[mi][2] = (m     < 128) ? *(const uint32_t*)&Q[m * 128 + kk + 8 + 2 * t4]       : 0u;
                fr[mi][3] = (m + 8 < 128) ? *(const uint32_t*)&Q[(m + 8) * 128 + kk + 8 + 2 * t4] : 0u;
            }
        };
        auto p2b_loadB = [&](int kk, uint32_t fr[3][4]) {
            int brow = kk + ((mat & 1) << 3) + l7;
#pragma unroll
            for (int ni = 0; ni < 3; ni++)
                ldmx4t(fr[ni], smaddr(&Ss[brow * GST + wn + ni * 16 + ((mat >> 1) << 3)]));
        };
        auto p3_loadA = [&](int base, int kk, uint32_t fr[3][4]) {
#pragma unroll
            for (int mi = 0; mi < 3; mi++) {
                int arow = base + wm + mi * 16 + ((mat & 1) << 3) + l7;
                ldmx4(fr[mi], smaddr(&Zh[arow * ZST + kk + ((mat >> 1) << 3)]));
            }
        };
        auto p3_loadB = [&](int kk, uint32_t fr[3][4]) {
            int brow = kk + ((mat & 1) << 3) + l7;
#pragma unroll
            for (int ni = 0; ni < 3; ni++)
                ldmx4t(fr[ni], smaddr(&Gs[brow * GST + wn + ni * 16 + ((mat >> 1) << 3)]));
        };
        auto zero_acc = [&]() {
#pragma unroll
            for (int a = 0; a < 3; a++)
#pragma unroll
                for (int c = 0; c < 3; c++)
#pragma unroll
                    for (int h = 0; h < 2; h++)
#pragma unroll
                        for (int e = 0; e < 4; e++) acc[a][c][h][e] = 0.0f;
        };
        auto do_mmas = [&](int cur) {
#pragma unroll
            for (int ni = 0; ni < 3; ni++)
#pragma unroll
                for (int mi = 0; mi < 3; mi++) {
                    mma16816(acc[mi][ni][0], afr[cur][mi], bfr[cur][ni] + 0);
                    mma16816(acc[mi][ni][1], afr[cur][mi], bfr[cur][ni] + 2);
                }
        };

        // ================= Phase 1: G = Zh[:256]^T Zh[:256] =================
        zero_acc();
        p1_loadA(0, afr[0]);
        p1_loadB(0, bfr[0]);
#pragma unroll 2
        for (int kk = 0; kk < 256; kk += 16) {
            int cur = (kk >> 4) & 1, nx = cur ^ 1;
            if (kk + 16 < 256) { p1_loadA(kk + 16, afr[nx]); p1_loadB(kk + 16, bfr[nx]); }
            do_mmas(cur);
        }
#pragma unroll
        for (int mi = 0; mi < 3; mi++)
#pragma unroll
            for (int ni = 0; ni < 3; ni++)
#pragma unroll
                for (int h = 0; h < 2; h++) {
                    float* c = acc[mi][ni][h];
                    int row = wm + mi * 16 + g;
                    int col = wn + ni * 16 + h * 8 + 2 * t4;
                    *(__nv_bfloat162*)&Gs[row * GST + col]       = pack2(c[0], c[1]);
                    *(__nv_bfloat162*)&Gs[(row + 8) * GST + col] = pack2(c[2], c[3]);
                }
        __syncthreads();

        // ================= Phase 2a: S = G @ P^T  (K=128) =================
        zero_acc();
        p2a_loadA(0, afr[0]);
        p2a_loadB(0, bfr[0]);
#pragma unroll
        for (int kk = 0; kk < 128; kk += 16) {
            int cur = (kk >> 4) & 1, nx = cur ^ 1;
            if (kk + 16 < 128) { p2a_loadA(kk + 16, afr[nx]); p2a_loadB(kk + 16, bfr[nx]); }
            do_mmas(cur);
        }
        // store S; fold in S[:,128] = G[:,128] (P_full's unit corner column)
#pragma unroll
        for (int mi = 0; mi < 3; mi++)
#pragma unroll
            for (int ni = 0; ni < 3; ni++)
#pragma unroll
                for (int h = 0; h < 2; h++) {
                    float* c = acc[mi][ni][h];
                    int row = wm + mi * 16 + g;
                    int col = wn + ni * 16 + h * 8 + 2 * t4;
                    __nv_bfloat162 v0 = pack2(c[0], c[1]);
                    __nv_bfloat162 v1 = pack2(c[2], c[3]);
                    if (col == 128) {
                        v0.x = Gs[row * GST + 128];
                        v1.x = Gs[(row + 8) * GST + 128];
                    }
                    *(__nv_bfloat162*)&Ss[row * GST + col]       = v0;
                    *(__nv_bfloat162*)&Ss[(row + 8) * GST + col] = v1;
                }
        __syncthreads();

        // ================= Phase 2b: W = Q @ S  (K=128, into Gs) ============
        zero_acc();
        p2b_loadA(0, afr[0]);
        p2b_loadB(0, bfr[0]);
#pragma unroll
        for (int kk = 0; kk < 128; kk += 16) {
            int cur = (kk >> 4) & 1, nx = cur ^ 1;
            if (kk + 16 < 128) { p2b_loadA(kk + 16, afr[nx]); p2b_loadB(kk + 16, bfr[nx]); }
            do_mmas(cur);
        }
#pragma unroll
        for (int mi = 0; mi < 3; mi++)
#pragma unroll
            for (int ni = 0; ni < 3; ni++)
#pragma unroll
                for (int h = 0; h < 2; h++) {
                    float* c = acc[mi][ni][h];
                    int row = wm + mi * 16 + g;
                    int col = wn + ni * 16 + h * 8 + 2 * t4;
                    *(__nv_bfloat162*)&Gs[row * GST + col]       = pack2(c[0], c[1]);
                    *(__nv_bfloat162*)&Gs[(row + 8) * GST + col] = pack2(c[2], c[3]);
                }
        __syncthreads();

        // ===== Phase 3: R = Zh @ W / 256  (K=128: W rows >=128 are exactly 0)
        // chunk 0: rows 0..143 ; chunk 1: rows 113..256 (outputs <144 dropped)
#pragma unroll
        for (int c0 = 0; c0 < 2; c0++) {
            int base = c0 ? 113 : 0;
            zero_acc();
            p3_loadA(base, 0, afr[0]);
            p3_loadB(0, bfr[0]);
#pragma unroll 2
            for (int kk = 0; kk < 128; kk += 16) {
                int cur = (kk >> 4) & 1, nx = cur ^ 1;
                if (kk + 16 < 128) { p3_loadA(base, kk + 16, afr[nx]); p3_loadB(kk + 16, bfr[nx]); }
                do_mmas(cur);
            }
            __syncthreads();   // all chunk GEMM reads of Zh done before writes

            const float inv = 1.0f / 256.0f;
#pragma unroll
            for (int mi = 0; mi < 3; mi++)
#pragma unroll
                for (int ni = 0; ni < 3; ni++)
#pragma unroll
                    for (int h = 0; h < 2; h++) {
                        float* cc = acc[mi][ni][h];
                        int row0 = wm + mi * 16 + g;
                        int col0 = wn + ni * 16 + h * 8 + 2 * t4;
#pragma unroll
                        for (int e = 0; e < 4; e++) {
                            int n = base + row0 + ((e >> 1) ? 8 : 0);
                            int j = col0 + (e & 1);
                            if (n < NP1 && j < DP1 && (c0 == 0 || n >= 144)) {
                                size_t fi = (size_t)n * DP1 + j;
                                float r = cc[e] * inv;
                                float a = __bfloat162float(Ac[n * AST + j]);
                                float zo = Zi[fi] + r + a;
                                Zo[fi]  = zo;
                                Ac[n * AST + j] =
                                    __float2bfloat16(a + r * gml[fi]);
                                Zh[n * ZST + j] = __float2bfloat16(zo);
                            }
                        }
                    }
            __syncthreads();
        }
    }
}

// ------------------------------ kernel_launch -------------------------------
extern "C" void kernel_launch(void* const* d_in, const int* in_sizes, int n_in,
                              void* d_out, int out_size) {
    const float* Z        = (const float*)d_in[0];
    const float* allparam = (const float*)d_in[1];
    const float* gamma    = (const float*)d_in[2];

    const int smem_bytes = (257 * ZST + 2 * 144 * GST + 257 * AST) * (int)sizeof(bf16);
    cudaFuncSetAttribute(k_fused, cudaFuncAttributeMaxDynamicSharedMemorySize,
                         smem_bytes);

    k_convPQ<<<(NLAYER * 2 * 128 * 128 + 255) / 256, 256>>>(allparam);
    k_fused<<<BATCH, 288, smem_bytes>>>(Z, gamma, (float*)d_out);
}

// round 10
// speedup vs baseline: 2.0741x; 1.0020x over previous
#include <cuda_runtime.h>
#include <cuda_bf16.h>
#include <cstdint>

#define BATCH  512
#define NP1    257
#define DP1    129
#define NLAYER 4
#define ZST    152     // Zh smem row stride (halves)
#define GST    152     // G/S/W smem row stride
#define AST    129     // acc smem row stride (scalar access only)

typedef __nv_bfloat16 bf16;

__device__ bf16 g_PQ[NLAYER * 2 * 128 * 128];   // bf16 P,Q weights

// ------------------------------ mma helpers --------------------------------
__device__ __forceinline__ uint32_t smaddr(const void* p) {
    return (uint32_t)__cvta_generic_to_shared(p);
}
__device__ __forceinline__ void ldmx4(uint32_t* r, uint32_t a) {
    asm volatile("ldmatrix.sync.aligned.m8n8.x4.shared.b16 {%0,%1,%2,%3}, [%4];"
                 : "=r"(r[0]), "=r"(r[1]), "=r"(r[2]), "=r"(r[3]) : "r"(a));
}
__device__ __forceinline__ void ldmx4t(uint32_t* r, uint32_t a) {
    asm volatile("ldmatrix.sync.aligned.m8n8.x4.trans.shared.b16 {%0,%1,%2,%3}, [%4];"
                 : "=r"(r[0]), "=r"(r[1]), "=r"(r[2]), "=r"(r[3]) : "r"(a));
}
__device__ __forceinline__ void mma16816(float* c, const uint32_t* a, const uint32_t* b) {
    asm volatile("mma.sync.aligned.m16n8k16.row.col.f32.bf16.bf16.f32 "
                 "{%0,%1,%2,%3}, {%4,%5,%6,%7}, {%8,%9}, {%0,%1,%2,%3};"
                 : "+f"(c[0]), "+f"(c[1]), "+f"(c[2]), "+f"(c[3])
                 : "r"(a[0]), "r"(a[1]), "r"(a[2]), "r"(a[3]), "r"(b[0]), "r"(b[1]));
}
__device__ __forceinline__ __nv_bfloat162 pack2(float a, float b) {
    __nv_bfloat162 v;
    v.x = __float2bfloat16(a);
    v.y = __float2bfloat16(b);
    return v;
}

// ------------------------------- convPQ -------------------------------------
__global__ void k_convPQ(const float* __restrict__ allparam) {
    int i = blockIdx.x * blockDim.x + threadIdx.x;
    if (i < NLAYER * 2 * 128 * 128) g_PQ[i] = __float2bfloat16(allparam[i]);
}

// ------------------------------- k_fused ------------------------------------
extern __shared__ bf16 sm_f[];

__global__ __launch_bounds__(288, 1) void k_fused(const float* __restrict__ Zin0,
                                                  const float* __restrict__ gamma,
                                                  float* __restrict__ Zio) {
    bf16* Zh = sm_f;                       // 257 x 152
    bf16* Gs = Zh + 257 * ZST;             // 144 x 152  (Gram, later W)
    bf16* Ss = Gs + 144 * GST;             // 144 x 152  (S = G P^T)
    bf16* Ac = Ss + 144 * GST;             // 257 x 129  (bf16 running acc)

    int b = blockIdx.x;
    const float* Zb0 = Zin0 + (size_t)b * NP1 * DP1;
    float*       Zo  = Zio  + (size_t)b * NP1 * DP1;

    int tid = threadIdx.x, lane = tid & 31, warp = tid >> 5;
    int wm = (warp / 3) * 48, wn = (warp % 3) * 48;
    int mat = lane >> 3, l7 = lane & 7;
    int g = lane >> 2, t4 = lane & 3;

    // ---------------- init: Zh from input Z; acc = 0 ----------------
    for (int i = tid; i < 257 * 38; i += 288) {
        int r = i / 38, c4 = (i % 38) * 4;
#pragma unroll
        for (int u = 0; u < 4; u++) {
            int j = c4 + u;
            float v = (j < DP1) ? Zb0[(size_t)r * DP1 + j] : 0.0f;
            Zh[r * ZST + j] = __float2bfloat16(v);
        }
    }
    for (int i = tid; i < 257 * AST; i += 288)
        Ac[i] = __float2bfloat16(0.0f);
    __syncthreads();

    float acc[3][3][2][4];
    uint32_t afr[2][3][4], bfr[2][3][4];

    for (int l = 0; l < NLAYER; l++) {
        const bf16* P = g_PQ + ((size_t)l * 2 + 0) * 128 * 128;
        const bf16* Q = g_PQ + ((size_t)l * 2 + 1) * 128 * 128;
        const float* gml = gamma + (size_t)l * NP1 * DP1;
        const float* Zi  = (l == 0) ? Zb0 : Zo;

        // -- fragment loaders (double-buffered call sites) --
        auto p1_loadA = [&](int kk, uint32_t fr[3][4]) {
            int arow = kk + ((mat >> 1) << 3) + l7;
#pragma unroll
            for (int mi = 0; mi < 3; mi++)
                ldmx4t(fr[mi], smaddr(&Zh[arow * ZST + wm + mi * 16 + ((mat & 1) << 3)]));
        };
        auto p1_loadB = [&](int kk, uint32_t fr[3][4]) {
            int brow = kk + ((mat & 1) << 3) + l7;
#pragma unroll
            for (int ni = 0; ni < 3; ni++)
                ldmx4t(fr[ni], smaddr(&Zh[brow * ZST + wn + ni * 16 + ((mat >> 1) << 3)]));
        };
        auto p2a_loadA = [&](int kk, uint32_t fr[3][4]) {
#pragma unroll
            for (int mi = 0; mi < 3; mi++) {
                int arow = wm + mi * 16 + ((mat & 1) << 3) + l7;
                ldmx4(fr[mi], smaddr(&Gs[arow * GST + kk + ((mat >> 1) << 3)]));
            }
        };
        auto p2a_loadB = [&](int kk, uint32_t fr[3][4]) {
#pragma unroll
            for (int ni = 0; ni < 3; ni++)
#pragma unroll
                for (int h = 0; h < 2; h++) {
                    int j = wn + ni * 16 + h * 8 + g;
                    if (j < 128) {
                        fr[ni][2 * h + 0] = *(const uint32_t*)&P[j * 128 + kk + 2 * t4];
                        fr[ni][2 * h + 1] = *(const uint32_t*)&P[j * 128 + kk + 8 + 2 * t4];
                    } else {
                        fr[ni][2 * h + 0] = 0u;
                        fr[ni][2 * h + 1] = 0u;
                    }
                }
        };
        auto p2b_loadA = [&](int kk, uint32_t fr[3][4]) {
#pragma unroll
            for (int mi = 0; mi < 3; mi++) {
                int m = wm + mi * 16 + g;
                fr[mi][0] = (m     < 128) ? *(const uint32_t*)&Q[m * 128 + kk + 2 * t4]           : 0u;
                fr[mi][1] = (m + 8 < 128) ? *(const uint32_t*)&Q[(m + 8) * 128 + kk + 2 * t4]     : 0u;
                fr[mi][2] = (m     < 128) ? *(const uint32_t*)&Q[m * 128 + kk + 8 + 2 * t4]       : 0u;
                fr[mi][3] = (m + 8 < 128) ? *(const uint32_t*)&Q[(m + 8) * 128 + kk + 8 + 2 * t4] : 0u;
            }
        };
        auto p2b_loadB = [&](int kk, uint32_t fr[3][4]) {
            int brow = kk + ((mat & 1) << 3) + l7;
#pragma unroll
            for (int ni = 0; ni < 3; ni++)
                ldmx4t(fr[ni], smaddr(&Ss[brow * GST + wn + ni * 16 + ((mat >> 1) << 3)]));
        };
        auto p3_loadA = [&](int base, int kk, uint32_t fr[3][4]) {
#pragma unroll
            for (int mi = 0; mi < 3; mi++) {
                int arow = base + wm + mi * 16 + ((mat & 1) << 3) + l7;
                ldmx4(fr[mi], smaddr(&Zh[arow * ZST + kk + ((mat >> 1) << 3)]));
            }
        };
        auto p3_loadB = [&](int kk, uint32_t fr[3][4]) {
            int brow = kk + ((mat & 1) << 3) + l7;
#pragma unroll
            for (int ni = 0; ni < 3; ni++)
                ldmx4t(fr[ni], smaddr(&Gs[brow * GST + wn + ni * 16 + ((mat >> 1) << 3)]));
        };
        auto zero_acc = [&]() {
#pragma unroll
            for (int a = 0; a < 3; a++)
#pragma unroll
                for (int c = 0; c < 3; c++)
#pragma unroll
                    for (int h = 0; h < 2; h++)
#pragma unroll
                        for (int e = 0; e < 4; e++) acc[a][c][h][e] = 0.0f;
        };
        auto do_mmas = [&](int cur) {
#pragma unroll
            for (int ni = 0; ni < 3; ni++)
#pragma unroll
                for (int mi = 0; mi < 3; mi++) {
                    mma16816(acc[mi][ni][0], afr[cur][mi], bfr[cur][ni] + 0);
                    mma16816(acc[mi][ni][1], afr[cur][mi], bfr[cur][ni] + 2);
                }
        };

        // ================= Phase 1: G = Zh[:256]^T Zh[:256] =================
        zero_acc();
        p1_loadA(0, afr[0]);
        p1_loadB(0, bfr[0]);
#pragma unroll 2
        for (int kk = 0; kk < 256; kk += 16) {
            int cur = (kk >> 4) & 1, nx = cur ^ 1;
            if (kk + 16 < 256) { p1_loadA(kk + 16, afr[nx]); p1_loadB(kk + 16, bfr[nx]); }
            do_mmas(cur);
        }
#pragma unroll
        for (int mi = 0; mi < 3; mi++)
#pragma unroll
            for (int ni = 0; ni < 3; ni++)
#pragma unroll
                for (int h = 0; h < 2; h++) {
                    float* c = acc[mi][ni][h];
                    int row = wm + mi * 16 + g;
                    int col = wn + ni * 16 + h * 8 + 2 * t4;
                    *(__nv_bfloat162*)&Gs[row * GST + col]       = pack2(c[0], c[1]);
                    *(__nv_bfloat162*)&Gs[(row + 8) * GST + col] = pack2(c[2], c[3]);
                }
        __syncthreads();

        // ================= Phase 2a: S = G @ P^T  (K=128) =================
        zero_acc();
        p2a_loadA(0, afr[0]);
        p2a_loadB(0, bfr[0]);
#pragma unroll
        for (int kk = 0; kk < 128; kk += 16) {
            int cur = (kk >> 4) & 1, nx = cur ^ 1;
            if (kk + 16 < 128) { p2a_loadA(kk + 16, afr[nx]); p2a_loadB(kk + 16, bfr[nx]); }
            do_mmas(cur);
        }
        // store S; fold in S[:,128] = G[:,128] (P_full's unit corner column)
#pragma unroll
        for (int mi = 0; mi < 3; mi++)
#pragma unroll
            for (int ni = 0; ni < 3; ni++)
#pragma unroll
                for (int h = 0; h < 2; h++) {
                    float* c = acc[mi][ni][h];
                    int row = wm + mi * 16 + g;
                    int col = wn + ni * 16 + h * 8 + 2 * t4;
                    __nv_bfloat162 v0 = pack2(c[0], c[1]);
                    __nv_bfloat162 v1 = pack2(c[2], c[3]);
                    if (col == 128) {
                        v0.x = Gs[row * GST + 128];
                        v1.x = Gs[(row + 8) * GST + 128];
                    }
                    *(__nv_bfloat162*)&Ss[row * GST + col]       = v0;
                    *(__nv_bfloat162*)&Ss[(row + 8) * GST + col] = v1;
                }
        __syncthreads();

        // ================= Phase 2b: W = Q @ S  (K=128, into Gs) ============
        zero_acc();
        p2b_loadA(0, afr[0]);
        p2b_loadB(0, bfr[0]);
#pragma unroll
        for (int kk = 0; kk < 128; kk += 16) {
            int cur = (kk >> 4) & 1, nx = cur ^ 1;
            if (kk + 16 < 128) { p2b_loadA(kk + 16, afr[nx]); p2b_loadB(kk + 16, bfr[nx]); }
            do_mmas(cur);
        }
#pragma unroll
        for (int mi = 0; mi < 3; mi++)
#pragma unroll
            for (int ni = 0; ni < 3; ni++)
#pragma unroll
                for (int h = 0; h < 2; h++) {
                    float* c = acc[mi][ni][h];
                    int row = wm + mi * 16 + g;
                    int col = wn + ni * 16 + h * 8 + 2 * t4;
                    *(__nv_bfloat162*)&Gs[row * GST + col]       = pack2(c[0], c[1]);
                    *(__nv_bfloat162*)&Gs[(row + 8) * GST + col] = pack2(c[2], c[3]);
                }
        __syncthreads();

        // ===== Phase 3: R = Zh @ W / 256  (K=128: W rows >=128 are exactly 0)
        // chunk 0: rows 0..143 ; chunk 1: rows 113..256 (outputs <144 dropped)
#pragma unroll
        for (int c0 = 0; c0 < 2; c0++) {
            int base = c0 ? 113 : 0;
            zero_acc();
            p3_loadA(base, 0, afr[0]);
            p3_loadB(0, bfr[0]);
#pragma unroll 2
            for (int kk = 0; kk < 128; kk += 16) {
                int cur = (kk >> 4) & 1, nx = cur ^ 1;
                if (kk + 16 < 128) { p3_loadA(base, kk + 16, afr[nx]); p3_loadB(kk + 16, bfr[nx]); }
                do_mmas(cur);
            }
            __syncthreads();   // all chunk GEMM reads of Zh done before writes

            const float inv = 1.0f / 256.0f;
#pragma unroll
            for (int mi = 0; mi < 3; mi++)
#pragma unroll
                for (int ni = 0; ni < 3; ni++)
#pragma unroll
                    for (int h = 0; h < 2; h++) {
                        float* cc = acc[mi][ni][h];
                        int row0 = wm + mi * 16 + g;
                        int col0 = wn + ni * 16 + h * 8 + 2 * t4;
#pragma unroll
                        for (int e = 0; e < 4; e++) {
                            int n = base + row0 + ((e >> 1) ? 8 : 0);
                            int j = col0 + (e & 1);
                            if (n < NP1 && j < DP1 && (c0 == 0 || n >= 144)) {
                                size_t fi = (size_t)n * DP1 + j;
                                float r = cc[e] * inv;
                                float a = __bfloat162float(Ac[n * AST + j]);
                                float zo = Zi[fi] + r + a;
                                Zo[fi]  = zo;
                                Ac[n * AST + j] =
                                    __float2bfloat16(a + r * gml[fi]);
                                Zh[n * ZST + j] = __float2bfloat16(zo);
                            }
                        }
                    }
            __syncthreads();
        }
    }
}

// ------------------------------ kernel_launch -------------------------------
extern "C" void kernel_launch(void* const* d_in, const int* in_sizes, int n_in,
                              void* d_out, int out_size) {
    const float* Z        = (const float*)d_in[0];
    const float* allparam = (const float*)d_in[1];
    const float* gamma    = (const float*)d_in[2];

    const int smem_bytes = (257 * ZST + 2 * 144 * GST + 257 * AST) * (int)sizeof(bf16);
    cudaFuncSetAttribute(k_fused, cudaFuncAttributeMaxDynamicSharedMemorySize,
                         smem_bytes);

    k_convPQ<<<(NLAYER * 2 * 128 * 128 + 255) / 256, 256>>>(allparam);
    k_fused<<<BATCH, 288, smem_bytes>>>(Z, gamma, (float*)d_out);
}